// round 1
// baseline (speedup 1.0000x reference)
#include <cuda_runtime.h>
#include <cstdint>

#define N_TOKENS   1000000
#define NFEAT      128
#define NCLUST     64
#define TILE_TOK   128
#define NUM_TILES  ((N_TOKENS + TILE_TOK - 1) / TILE_TOK)   // 7813
#define GRID_MAIN  296
#define GB_STRIDE  16   // u64 stride between g_best entries -> 128B apart (LTS spread)

// Global scratch: per-cluster best key = (monotonic float bits << 32) | token index
__device__ unsigned long long g_best[NCLUST * GB_STRIDE];

__global__ void init_kernel() {
    int i = threadIdx.x;
    if (i < NCLUST) g_best[i * GB_STRIDE] = 0xFFFFFFFFFFFFFFFFull;
}

__device__ __forceinline__ unsigned long long pack_key(float f, unsigned idx) {
    unsigned u = __float_as_uint(f);
    // monotonic mapping: order of uint == order of float (handles negatives)
    u = (u & 0x80000000u) ? ~u : (u | 0x80000000u);
    return ((unsigned long long)u << 32) | (unsigned long long)idx;
}

__global__ __launch_bounds__(256, 2)
void cluster_main(const float* __restrict__ x, const float* __restrict__ cc) {
    extern __shared__ float smem[];
    float* x_s = smem;                          // [tok][d]  128x128 (token-major)
    float* c_s = smem + TILE_TOK * NFEAT;       // [d][k]    128x64  (d-major)
    unsigned long long* best_blk =
        (unsigned long long*)(c_s + NFEAT * NCLUST);  // [64]

    const int tid = threadIdx.x;
    const int tx  = tid & 15;    // cluster group: clusters tx*4 .. tx*4+3
    const int ty  = tid >> 4;    // token group:   tokens  ty*8 .. ty*8+7 (within tile)

    // Load centers transposed into smem (one-time; minor conflicts OK)
    for (int i = tid; i < NCLUST * NFEAT; i += 256) {
        int k = i >> 7;         // cluster
        int d = i & 127;        // feature
        c_s[d * NCLUST + k] = cc[i];
    }
    if (tid < NCLUST) best_blk[tid] = 0xFFFFFFFFFFFFFFFFull;

    float    bestd[4] = {__int_as_float(0x7f800000), __int_as_float(0x7f800000),
                         __int_as_float(0x7f800000), __int_as_float(0x7f800000)};
    unsigned besti[4] = {0u, 0u, 0u, 0u};

    const float4* xg  = (const float4*)x;
    const float4* cs4 = (const float4*)c_s;     // row d = 16 float4 (64 clusters)

    for (int tile = blockIdx.x; tile < NUM_TILES; tile += GRID_MAIN) {
        const int tokBase = tile * TILE_TOK;

        __syncthreads();   // previous tile's compute done before overwrite
        // ---- stage x tile: 4096 float4, coalesced global, conflict-free STS ----
        {
            float4* xs4 = (float4*)x_s;
            #pragma unroll
            for (int i = 0; i < 16; ++i) {
                int f   = tid + i * 256;       // 0..4095
                int tok = f >> 5;              // 32 float4 per token
                int dq  = f & 31;
                int gtok = tokBase + tok;
                if (gtok >= N_TOKENS) gtok = N_TOKENS - 1;  // clamp (excluded later)
                xs4[f] = xg[(size_t)gtok * 32 + dq];
            }
        }
        __syncthreads();

        // ---- register-tiled dot products: 8 tokens x 4 clusters ----
        float acc[8][4];
        #pragma unroll
        for (int i = 0; i < 8; ++i)
            #pragma unroll
            for (int j = 0; j < 4; ++j) acc[i][j] = 0.f;

        #pragma unroll 2
        for (int d = 0; d < NFEAT; d += 4) {
            float4 c0 = cs4[(d + 0) * 16 + tx];
            float4 c1 = cs4[(d + 1) * 16 + tx];
            float4 c2 = cs4[(d + 2) * 16 + tx];
            float4 c3 = cs4[(d + 3) * 16 + tx];
            #pragma unroll
            for (int i = 0; i < 8; ++i) {
                float4 xq = *(const float4*)(x_s + (ty * 8 + i) * NFEAT + d);
                acc[i][0] = fmaf(xq.x, c0.x, acc[i][0]);
                acc[i][0] = fmaf(xq.y, c1.x, acc[i][0]);
                acc[i][0] = fmaf(xq.z, c2.x, acc[i][0]);
                acc[i][0] = fmaf(xq.w, c3.x, acc[i][0]);
                acc[i][1] = fmaf(xq.x, c0.y, acc[i][1]);
                acc[i][1] = fmaf(xq.y, c1.y, acc[i][1]);
                acc[i][1] = fmaf(xq.z, c2.y, acc[i][1]);
                acc[i][1] = fmaf(xq.w, c3.y, acc[i][1]);
                acc[i][2] = fmaf(xq.x, c0.z, acc[i][2]);
                acc[i][2] = fmaf(xq.y, c1.z, acc[i][2]);
                acc[i][2] = fmaf(xq.z, c2.z, acc[i][2]);
                acc[i][2] = fmaf(xq.w, c3.z, acc[i][2]);
                acc[i][3] = fmaf(xq.x, c0.w, acc[i][3]);
                acc[i][3] = fmaf(xq.y, c1.w, acc[i][3]);
                acc[i][3] = fmaf(xq.z, c2.w, acc[i][3]);
                acc[i][3] = fmaf(xq.w, c3.w, acc[i][3]);
            }
        }

        // ---- per-token x^2: each lane squares its 8-feature slice, butterfly over 16 lanes ----
        float xs2[8];
        #pragma unroll
        for (int i = 0; i < 8; ++i) {
            const float* xr = x_s + (ty * 8 + i) * NFEAT + tx * 8;
            float4 a = *(const float4*)(xr);
            float4 b = *(const float4*)(xr + 4);
            float s = a.x * a.x;
            s = fmaf(a.y, a.y, s);
            s = fmaf(a.z, a.z, s);
            s = fmaf(a.w, a.w, s);
            s = fmaf(b.x, b.x, s);
            s = fmaf(b.y, b.y, s);
            s = fmaf(b.z, b.z, s);
            s = fmaf(b.w, b.w, s);
            xs2[i] = s;
        }
        #pragma unroll
        for (int sh = 1; sh < 16; sh <<= 1) {
            #pragma unroll
            for (int i = 0; i < 8; ++i)
                xs2[i] += __shfl_xor_sync(0xffffffffu, xs2[i], sh);
        }

        // ---- argmin update: score = x^2 - 2*dot  (c^2 dropped: constant per cluster) ----
        #pragma unroll
        for (int i = 0; i < 8; ++i) {
            int gtok = tokBase + ty * 8 + i;
            if (gtok < N_TOKENS) {
                #pragma unroll
                for (int j = 0; j < 4; ++j) {
                    float s = fmaf(-2.f, acc[i][j], xs2[i]);
                    if (s < bestd[j]) { bestd[j] = s; besti[j] = (unsigned)gtok; }
                }
            }
        }
    }

    // ---- block-level merge, then one global atomic per cluster per block ----
    #pragma unroll
    for (int j = 0; j < 4; ++j)
        atomicMin(&best_blk[tx * 4 + j], pack_key(bestd[j], besti[j]));
    __syncthreads();
    if (tid < NCLUST)
        atomicMin(&g_best[tid * GB_STRIDE], best_blk[tid]);
}

__global__ void gather_kernel(const float* __restrict__ x, float* __restrict__ out) {
    int k = blockIdx.x;
    unsigned idx = (unsigned)(g_best[k * GB_STRIDE] & 0xFFFFFFFFull);
    out[k * NFEAT + threadIdx.x] = x[(size_t)idx * NFEAT + threadIdx.x];
}

extern "C" void kernel_launch(void* const* d_in, const int* in_sizes, int n_in,
                              void* d_out, int out_size) {
    const float* x;
    const float* cc;
    // metadata order: x (1,1e6,128) then cluster_centers (64,128); guard anyway
    if (n_in >= 2 && in_sizes[0] == NCLUST * NFEAT) {
        cc = (const float*)d_in[0];
        x  = (const float*)d_in[1];
    } else {
        x  = (const float*)d_in[0];
        cc = (const float*)d_in[1];
    }
    float* out = (float*)d_out;

    size_t shmem = (size_t)(TILE_TOK * NFEAT + NFEAT * NCLUST) * sizeof(float)
                 + NCLUST * sizeof(unsigned long long);   // 98816 B
    cudaFuncSetAttribute(cluster_main,
                         cudaFuncAttributeMaxDynamicSharedMemorySize, (int)shmem);

    init_kernel<<<1, 64>>>();
    cluster_main<<<GRID_MAIN, 256, shmem>>>(x, cc);
    gather_kernel<<<NCLUST, NFEAT>>>(x, out);
}

// round 3
// speedup vs baseline: 1.1234x; 1.1234x over previous
#include <cuda_runtime.h>
#include <cuda_fp16.h>
#include <cstdint>

#define N_TOKENS   1000000
#define NFEAT      128
#define NCLUST     64
#define TILE_TOK   128
#define NUM_TILES  ((N_TOKENS + TILE_TOK - 1) / TILE_TOK)   // 7813
#define GRID_MAIN  148
#define GB_STRIDE  16

// ---- smem layout (byte offsets). Rows are 256B (128 fp16); 16B chunks swizzled.
#define SM_XHI   0
#define SM_XLO   32768
#define SM_CHI   65536
#define SM_CLO   81920
#define SM_X2    98304                       // 128 f32
#define SM_BEST  (SM_X2 + 512)               // 64 u64
#define SM_TOTAL (SM_BEST + 512 + 128)

__device__ unsigned long long g_best[NCLUST * GB_STRIDE];

__global__ void init_kernel() {
    int i = threadIdx.x;
    if (i < NCLUST) g_best[i * GB_STRIDE] = 0xFFFFFFFFFFFFFFFFull;
}

__device__ __forceinline__ uint32_t smem_u32(const void* p) {
    uint32_t a;
    asm("{ .reg .u64 t; cvta.to.shared.u64 t, %1; cvt.u32.u64 %0, t; }" : "=r"(a) : "l"(p));
    return a;
}

__device__ __forceinline__ void ldsm4(uint32_t (&r)[4], uint32_t addr) {
    asm volatile("ldmatrix.sync.aligned.m8n8.x4.shared.b16 {%0,%1,%2,%3}, [%4];"
        : "=r"(r[0]), "=r"(r[1]), "=r"(r[2]), "=r"(r[3]) : "r"(addr));
}

__device__ __forceinline__ void mma16816(float (&d)[4], const uint32_t (&a)[4],
                                         uint32_t b0, uint32_t b1) {
    asm volatile("mma.sync.aligned.m16n8k16.row.col.f32.f16.f16.f32 "
        "{%0,%1,%2,%3}, {%4,%5,%6,%7}, {%8,%9}, {%0,%1,%2,%3};"
        : "+f"(d[0]), "+f"(d[1]), "+f"(d[2]), "+f"(d[3])
        : "r"(a[0]), "r"(a[1]), "r"(a[2]), "r"(a[3]), "r"(b0), "r"(b1));
}

__device__ __forceinline__ unsigned long long pack_key(float f, unsigned idx) {
    unsigned u = __float_as_uint(f);
    u = (u & 0x80000000u) ? ~u : (u | 0x80000000u);
    return ((unsigned long long)u << 32) | (unsigned long long)idx;
}

__device__ __forceinline__ uint32_t pack_h2(__half a, __half b) {
    return (uint32_t)__half_as_ushort(a) | ((uint32_t)__half_as_ushort(b) << 16);
}

// Convert 64 contiguous fp32 (one half-row) into hi/lo fp16 smem tiles
// (256B rows, 16B chunks XOR-swizzled by row&7). Returns sum of squares.
__device__ __forceinline__ float cvt_row64(const float4* f4, char* smem,
                                           uint32_t hi_off, uint32_t lo_off,
                                           int row, int half) {
    float ss = 0.f;
    const uint32_t rb = (uint32_t)row * 256;
    #pragma unroll
    for (int c = 0; c < 8; ++c) {
        float e[8];
        float4 a = f4[2 * c], b = f4[2 * c + 1];
        e[0] = a.x; e[1] = a.y; e[2] = a.z; e[3] = a.w;
        e[4] = b.x; e[5] = b.y; e[6] = b.z; e[7] = b.w;
        __half hh[8], hl[8];
        #pragma unroll
        for (int t = 0; t < 8; ++t) {
            float x0 = e[t];
            ss = fmaf(x0, x0, ss);
            __half h = __float2half_rn(x0);
            float r = x0 - __half2float(h);
            hh[t] = h;
            hl[t] = __float2half_rn(r);
        }
        uint32_t phys = (uint32_t)(((half * 8 + c) ^ (row & 7)) * 16);
        uint4 vh, vl;
        vh.x = pack_h2(hh[0], hh[1]); vh.y = pack_h2(hh[2], hh[3]);
        vh.z = pack_h2(hh[4], hh[5]); vh.w = pack_h2(hh[6], hh[7]);
        vl.x = pack_h2(hl[0], hl[1]); vl.y = pack_h2(hl[2], hl[3]);
        vl.z = pack_h2(hl[4], hl[5]); vl.w = pack_h2(hl[6], hl[7]);
        *(uint4*)(smem + hi_off + rb + phys) = vh;
        *(uint4*)(smem + lo_off + rb + phys) = vl;
    }
    return ss;
}

__global__ __launch_bounds__(256, 1)
void cluster_main(const float* __restrict__ x, const float* __restrict__ cc) {
    extern __shared__ char smem[];
    const uint32_t sm = smem_u32(smem);
    const int tid  = threadIdx.x;
    const int wid  = tid >> 5;
    const int lane = tid & 31;
    const int crow = tid >> 1;   // conversion: token row 0..127
    const int chal = tid & 1;    // conversion: K half

    // warp tile: 32 tokens x 32 clusters
    const int tb = (wid >> 1) * 32;   // token base within tile
    const int cb = (wid & 1) * 32;    // cluster base

    float* x2s = (float*)(smem + SM_X2);
    unsigned long long* best_blk = (unsigned long long*)(smem + SM_BEST);
    if (tid < NCLUST) best_blk[tid] = 0xFFFFFFFFFFFFFFFFull;

    // ---- convert centers (once): 64 rows x 128 feat -> CHI/CLO ----
    if (tid < 128) {
        int rr = tid >> 1, hh = tid & 1;
        float4 cf4[16];
        const float4* cg4 = (const float4*)cc;
        #pragma unroll
        for (int j = 0; j < 16; ++j) cf4[j] = cg4[rr * 32 + hh * 16 + j];
        (void)cvt_row64(cf4, smem, SM_CHI, SM_CLO, rr, hh);
    }

    // ---- precomputed ldmatrix lane addressing ----
    const int rowA  = tb + (lane & 15);          // + mt*16
    const int khA   = lane >> 4;                 // A k-half
    const int nrowB = cb + (lane & 7) + ((lane >> 4) & 1) * 8;  // + np*16
    const int khB   = (lane >> 3) & 1;           // B k-half

    float    bestd[8];
    unsigned besti[8];
    #pragma unroll
    for (int j = 0; j < 8; ++j) { bestd[j] = __int_as_float(0x7f800000); besti[j] = 0u; }

    const float4* xg4 = (const float4*)x;

    int ntiles = 0;
    for (int t = blockIdx.x; t < NUM_TILES; t += GRID_MAIN) ++ntiles;

    // prefetch first tile
    float4 f4[16];
    int tile = blockIdx.x;
    if (ntiles > 0) {
        int gtok = tile * TILE_TOK + crow;
        if (gtok >= N_TOKENS) gtok = N_TOKENS - 1;
        #pragma unroll
        for (int j = 0; j < 16; ++j) f4[j] = xg4[(size_t)gtok * 32 + chal * 16 + j];
    }
    __syncthreads();   // centers + best_blk ready

    for (int it = 0; it < ntiles; ++it, tile += GRID_MAIN) {
        const int tokBase = tile * TILE_TOK;

        // ---- convert x tile -> XHI/XLO; fused x^2 ----
        float ss = cvt_row64(f4, smem, SM_XHI, SM_XLO, crow, chal);
        float tot = ss + __shfl_xor_sync(0xffffffffu, ss, 1);
        if (chal == 0) x2s[crow] = tot;
        __syncthreads();

        // ---- prefetch next tile (DRAM latency hides under MMA) ----
        if (it + 1 < ntiles) {
            int gtok = (tile + GRID_MAIN) * TILE_TOK + crow;
            if (gtok >= N_TOKENS) gtok = N_TOKENS - 1;
            #pragma unroll
            for (int j = 0; j < 16; ++j) f4[j] = xg4[(size_t)gtok * 32 + chal * 16 + j];
        }

        // ---- MMA: 3 split terms x 8 k-steps; D accumulates in registers ----
        float d[2][4][4];
        #pragma unroll
        for (int mt = 0; mt < 2; ++mt)
            #pragma unroll
            for (int nt = 0; nt < 4; ++nt)
                #pragma unroll
                for (int i = 0; i < 4; ++i) d[mt][nt][i] = 0.f;

        #pragma unroll
        for (int term = 0; term < 3; ++term) {
            const uint32_t abase = sm + ((term == 2) ? SM_XLO : SM_XHI);
            const uint32_t bbase = sm + ((term == 1) ? SM_CLO : SM_CHI);
            #pragma unroll
            for (int k = 0; k < 8; ++k) {
                uint32_t aF[2][4], bF[2][4];
                const int ca = 2 * k + khA;
                const int cbk = 2 * k + khB;
                #pragma unroll
                for (int mt = 0; mt < 2; ++mt) {
                    int r = rowA + mt * 16;
                    ldsm4(aF[mt], abase + (uint32_t)(r * 256 + ((ca ^ (r & 7)) * 16)));
                }
                #pragma unroll
                for (int np = 0; np < 2; ++np) {
                    int r = nrowB + np * 16;
                    ldsm4(bF[np], bbase + (uint32_t)(r * 256 + ((cbk ^ (r & 7)) * 16)));
                }
                #pragma unroll
                for (int mt = 0; mt < 2; ++mt) {
                    mma16816(d[mt][0], aF[mt], bF[0][0], bF[0][1]);
                    mma16816(d[mt][1], aF[mt], bF[0][2], bF[0][3]);
                    mma16816(d[mt][2], aF[mt], bF[1][0], bF[1][1]);
                    mma16816(d[mt][3], aF[mt], bF[1][2], bF[1][3]);
                }
            }
        }

        // ---- epilogue: score = x^2 - 2*dot; per-lane argmin over 8 cols ----
        #pragma unroll
        for (int mt = 0; mt < 2; ++mt) {
            #pragma unroll
            for (int h = 0; h < 2; ++h) {
                const int tloc = tb + mt * 16 + (lane >> 2) + h * 8;
                const int gtok = tokBase + tloc;
                if (gtok < N_TOKENS) {
                    const float xv = x2s[tloc];
                    #pragma unroll
                    for (int nt = 0; nt < 4; ++nt) {
                        #pragma unroll
                        for (int p = 0; p < 2; ++p) {
                            float s = fmaf(-2.f, d[mt][nt][h * 2 + p], xv);
                            int j = nt * 2 + p;
                            if (s < bestd[j]) { bestd[j] = s; besti[j] = (unsigned)gtok; }
                        }
                    }
                }
            }
        }
        __syncthreads();   // all warps done reading tile before next convert
    }

    // ---- merge: shfl-xor across the 8 lanes sharing each column ----
    #pragma unroll
    for (int j = 0; j < 8; ++j) {
        unsigned long long key = pack_key(bestd[j], besti[j]);
        #pragma unroll
        for (int off = 4; off < 32; off <<= 1) {
            unsigned long long o = __shfl_xor_sync(0xffffffffu, key, off);
            if (o < key) key = o;
        }
        if ((lane >> 2) == 0) {
            int cl = cb + (j >> 1) * 8 + 2 * (lane & 3) + (j & 1);
            atomicMin(&best_blk[cl], key);
        }
    }
    __syncthreads();
    if (tid < NCLUST)
        atomicMin(&g_best[tid * GB_STRIDE], best_blk[tid]);
}

__global__ void gather_kernel(const float* __restrict__ x, float* __restrict__ out) {
    int k = blockIdx.x;
    unsigned idx = (unsigned)(g_best[k * GB_STRIDE] & 0xFFFFFFFFull);
    out[k * NFEAT + threadIdx.x] = x[(size_t)idx * NFEAT + threadIdx.x];
}

extern "C" void kernel_launch(void* const* d_in, const int* in_sizes, int n_in,
                              void* d_out, int out_size) {
    const float* x;
    const float* cc;
    if (n_in >= 2 && in_sizes[0] == NCLUST * NFEAT) {
        cc = (const float*)d_in[0];
        x  = (const float*)d_in[1];
    } else {
        x  = (const float*)d_in[0];
        cc = (const float*)d_in[1];
    }
    float* out = (float*)d_out;

    cudaFuncSetAttribute(cluster_main,
                         cudaFuncAttributeMaxDynamicSharedMemorySize, SM_TOTAL);

    init_kernel<<<1, 64>>>();
    cluster_main<<<GRID_MAIN, 256, SM_TOTAL>>>(x, cc);
    gather_kernel<<<NCLUST, NFEAT>>>(x, out);
}

// round 4
// speedup vs baseline: 1.7580x; 1.5649x over previous
#include <cuda_runtime.h>
#include <cuda_fp16.h>
#include <cstdint>

#define N_TOKENS   1000000
#define NFEAT      128
#define NCLUST     64
#define TILE_TOK   128
#define NUM_TILES  ((N_TOKENS + TILE_TOK - 1) / TILE_TOK)   // 7813
#define GRID_MAIN  148
#define GB_STRIDE  16

// ---- smem layout (byte offsets) ----
// RAW: 2 x (128 tok x 512B) fp32 staging, 16B-chunk swizzled
// XHI/XLO: 128 x 256B fp16 tiles; CHI/CLO: 64 x 256B fp16 tiles (ldmatrix swizzle)
#define SM_RAW   0
#define SM_XHI   131072
#define SM_XLO   (SM_XHI + 32768)
#define SM_CHI   (SM_XLO + 32768)
#define SM_CLO   (SM_CHI + 16384)
#define SM_X2    (SM_CLO + 16384)            // 128 f32
#define SM_BEST  (SM_X2 + 512)               // 64 u64
#define SM_TOTAL (SM_BEST + 512)             // 230400 <= 232448

// zero-initialized; stores ~key so empty slot (0) == +inf; merged with atomicMax
__device__ unsigned long long g_best[NCLUST * GB_STRIDE];

__device__ __forceinline__ uint32_t smem_u32(const void* p) {
    uint32_t a;
    asm("{ .reg .u64 t; cvta.to.shared.u64 t, %1; cvt.u32.u64 %0, t; }" : "=r"(a) : "l"(p));
    return a;
}
__device__ __forceinline__ void cp_async16(uint32_t dst, const void* src) {
    asm volatile("cp.async.cg.shared.global [%0], [%1], 16;" :: "r"(dst), "l"(src));
}
#define CP_COMMIT() asm volatile("cp.async.commit_group;" ::: "memory")
#define CP_WAIT1()  asm volatile("cp.async.wait_group 1;" ::: "memory")

__device__ __forceinline__ void ldsm4(uint32_t (&r)[4], uint32_t addr) {
    asm volatile("ldmatrix.sync.aligned.m8n8.x4.shared.b16 {%0,%1,%2,%3}, [%4];"
        : "=r"(r[0]), "=r"(r[1]), "=r"(r[2]), "=r"(r[3]) : "r"(addr));
}
__device__ __forceinline__ void mma16816(float (&d)[4], const uint32_t (&a)[4],
                                         uint32_t b0, uint32_t b1) {
    asm volatile("mma.sync.aligned.m16n8k16.row.col.f32.f16.f16.f32 "
        "{%0,%1,%2,%3}, {%4,%5,%6,%7}, {%8,%9}, {%0,%1,%2,%3};"
        : "+f"(d[0]), "+f"(d[1]), "+f"(d[2]), "+f"(d[3])
        : "r"(a[0]), "r"(a[1]), "r"(a[2]), "r"(a[3]), "r"(b0), "r"(b1));
}

// inverted monotonic key: LARGER inv == better (smaller score, then smaller idx)
__device__ __forceinline__ unsigned long long inv_key(float f, unsigned idx) {
    unsigned u = __float_as_uint(f);
    u = (u & 0x80000000u) ? ~u : (u | 0x80000000u);
    return ~(((unsigned long long)u << 32) | (unsigned long long)idx);
}
__device__ __forceinline__ uint32_t pack_h2(__half a, __half b) {
    return (uint32_t)__half_as_ushort(a) | ((uint32_t)__half_as_ushort(b) << 16);
}

// Convert 8 fp32 -> one 16B hi chunk + one 16B lo chunk; accumulate sum of squares.
__device__ __forceinline__ void cvt8(const float* e, uint4& vh, uint4& vl, float& ss) {
    __half hh[8], hl[8];
    #pragma unroll
    for (int t = 0; t < 8; ++t) {
        float x0 = e[t];
        ss = fmaf(x0, x0, ss);
        __half h = __float2half_rn(x0);
        float r = x0 - __half2float(h);
        hh[t] = h;
        hl[t] = __float2half_rn(r);
    }
    vh.x = pack_h2(hh[0], hh[1]); vh.y = pack_h2(hh[2], hh[3]);
    vh.z = pack_h2(hh[4], hh[5]); vh.w = pack_h2(hh[6], hh[7]);
    vl.x = pack_h2(hl[0], hl[1]); vl.y = pack_h2(hl[2], hl[3]);
    vl.z = pack_h2(hl[4], hl[5]); vl.w = pack_h2(hl[6], hl[7]);
}

__global__ __launch_bounds__(256, 1)
void cluster_main(const float* __restrict__ x, const float* __restrict__ cc) {
    extern __shared__ char smem[];
    const uint32_t sm = smem_u32(smem);
    const int tid  = threadIdx.x;
    const int wid  = tid >> 5;
    const int lane = tid & 31;
    const int crow = tid >> 1;   // conversion: token row 0..127
    const int chal = tid & 1;    // conversion: K half

    const int tb = (wid >> 1) * 32;   // warp token base
    const int cb = (wid & 1) * 32;    // warp cluster base

    float* x2s = (float*)(smem + SM_X2);
    unsigned long long* best_blk = (unsigned long long*)(smem + SM_BEST);
    if (tid < NCLUST) best_blk[tid] = 0ull;

    // ---- convert centers (once) ----
    if (tid < 128) {
        int rr = tid >> 1, hh = tid & 1;
        const float* cg = cc + rr * NFEAT + hh * 64;
        float dummy = 0.f;
        #pragma unroll
        for (int c = 0; c < 8; ++c) {
            float e[8];
            #pragma unroll
            for (int t = 0; t < 8; ++t) e[t] = cg[c * 8 + t];
            uint4 vh, vl;
            cvt8(e, vh, vl, dummy);
            uint32_t phys = (uint32_t)(((hh * 8 + c) ^ (rr & 7)) * 16) + (uint32_t)rr * 256;
            *(uint4*)(smem + SM_CHI + phys) = vh;
            *(uint4*)(smem + SM_CLO + phys) = vl;
        }
    }

    // ---- ldmatrix lane addressing (identical to R3) ----
    const int rowA  = tb + (lane & 15);
    const int khA   = lane >> 4;
    const int nrowB = cb + (lane & 7) + ((lane >> 4) & 1) * 8;
    const int khB   = (lane >> 3) & 1;

    float    bestd[8];
    unsigned besti[8];
    #pragma unroll
    for (int j = 0; j < 8; ++j) { bestd[j] = __int_as_float(0x7f800000); besti[j] = 0u; }

    const float4* xg4 = (const float4*)x;

    int ntiles = 0;
    for (int t = blockIdx.x; t < NUM_TILES; t += GRID_MAIN) ++ntiles;

    // ---- cp.async issue helper (one full tile -> raw[buf]) ----
    auto issue_tile = [&](int tile_idx, int buf) {
        const int tokBase = tile_idx * TILE_TOK;
        const uint32_t base = sm + SM_RAW + (uint32_t)buf * 65536;
        #pragma unroll
        for (int i = 0; i < 16; ++i) {
            int f   = tid + i * 256;
            int tok = f >> 5;
            int dq  = f & 31;
            int gtok = tokBase + tok;
            if (gtok >= N_TOKENS) gtok = N_TOKENS - 1;
            uint32_t dst = base + (uint32_t)tok * 512
                         + (uint32_t)((dq ^ (((tok & 3) << 1) | (dq >> 4))) * 16);
            cp_async16(dst, xg4 + (size_t)gtok * 32 + dq);
        }
    };

    // prologue: prefetch tile 0
    int tile = blockIdx.x;
    if (ntiles > 0) issue_tile(tile, 0);
    CP_COMMIT();

    for (int it = 0; it < ntiles; ++it, tile += GRID_MAIN) {
        const int tokBase = tile * TILE_TOK;
        const int buf = it & 1;

        // prefetch next tile into other buffer (raw[buf^1] free: convert(it-1) done)
        if (it + 1 < ntiles) issue_tile(tile + GRID_MAIN, buf ^ 1);
        CP_COMMIT();
        CP_WAIT1();          // tile it resident
        __syncthreads();

        // ---- convert raw[buf] -> XHI/XLO; fused x^2 ----
        {
            const char* raw = smem + SM_RAW + (size_t)buf * 65536 + (size_t)crow * 512;
            const int xorv = ((crow & 3) << 1) | chal;
            float ss = 0.f;
            #pragma unroll
            for (int c = 0; c < 8; ++c) {
                int a0 = chal * 16 + 2 * c;
                float e[8];
                *(float4*)(e)     = *(const float4*)(raw + ((a0       ^ xorv) * 16));
                *(float4*)(e + 4) = *(const float4*)(raw + (((a0 + 1) ^ xorv) * 16));
                uint4 vh, vl;
                cvt8(e, vh, vl, ss);
                uint32_t phys = (uint32_t)crow * 256
                              + (uint32_t)(((chal * 8 + c) ^ (crow & 7)) * 16);
                *(uint4*)(smem + SM_XHI + phys) = vh;
                *(uint4*)(smem + SM_XLO + phys) = vl;
            }
            float tot = ss + __shfl_xor_sync(0xffffffffu, ss, 1);
            if (chal == 0) x2s[crow] = tot;
        }
        __syncthreads();

        // ---- MMA: 3 split terms x 8 k-steps ----
        float d[2][4][4];
        #pragma unroll
        for (int mt = 0; mt < 2; ++mt)
            #pragma unroll
            for (int nt = 0; nt < 4; ++nt)
                #pragma unroll
                for (int i = 0; i < 4; ++i) d[mt][nt][i] = 0.f;

        #pragma unroll
        for (int term = 0; term < 3; ++term) {
            const uint32_t abase = sm + ((term == 2) ? SM_XLO : SM_XHI);
            const uint32_t bbase = sm + ((term == 1) ? SM_CLO : SM_CHI);
            #pragma unroll
            for (int k = 0; k < 8; ++k) {
                uint32_t aF[2][4], bF[2][4];
                const int ca  = 2 * k + khA;
                const int cbk = 2 * k + khB;
                #pragma unroll
                for (int mt = 0; mt < 2; ++mt) {
                    int r = rowA + mt * 16;
                    ldsm4(aF[mt], abase + (uint32_t)(r * 256 + ((ca ^ (r & 7)) * 16)));
                }
                #pragma unroll
                for (int np = 0; np < 2; ++np) {
                    int r = nrowB + np * 16;
                    ldsm4(bF[np], bbase + (uint32_t)(r * 256 + ((cbk ^ (r & 7)) * 16)));
                }
                #pragma unroll
                for (int mt = 0; mt < 2; ++mt) {
                    mma16816(d[mt][0], aF[mt], bF[0][0], bF[0][1]);
                    mma16816(d[mt][1], aF[mt], bF[0][2], bF[0][3]);
                    mma16816(d[mt][2], aF[mt], bF[1][0], bF[1][1]);
                    mma16816(d[mt][3], aF[mt], bF[1][2], bF[1][3]);
                }
            }
        }

        // ---- epilogue: score = x^2 - 2*dot; running argmin ----
        #pragma unroll
        for (int mt = 0; mt < 2; ++mt) {
            #pragma unroll
            for (int h = 0; h < 2; ++h) {
                const int tloc = tb + mt * 16 + (lane >> 2) + h * 8;
                const int gtok = tokBase + tloc;
                if (gtok < N_TOKENS) {
                    const float xv = x2s[tloc];
                    #pragma unroll
                    for (int nt = 0; nt < 4; ++nt) {
                        #pragma unroll
                        for (int p = 0; p < 2; ++p) {
                            float s = fmaf(-2.f, d[mt][nt][h * 2 + p], xv);
                            int j = nt * 2 + p;
                            if (s < bestd[j]) { bestd[j] = s; besti[j] = (unsigned)gtok; }
                        }
                    }
                }
            }
        }
        __syncthreads();   // all LDSM reads of this tile done before next convert
    }

    // ---- merge: shfl reduce (max of inverted key) then atomics ----
    #pragma unroll
    for (int j = 0; j < 8; ++j) {
        unsigned long long key = inv_key(bestd[j], besti[j]);
        #pragma unroll
        for (int off = 4; off < 32; off <<= 1) {
            unsigned long long o = __shfl_xor_sync(0xffffffffu, key, off);
            if (o > key) key = o;
        }
        if ((lane >> 2) == 0) {
            int cl = cb + (j >> 1) * 8 + 2 * (lane & 3) + (j & 1);
            atomicMax(&best_blk[cl], key);
        }
    }
    __syncthreads();
    if (tid < NCLUST)
        atomicMax(&g_best[tid * GB_STRIDE], best_blk[tid]);
}

__global__ void gather_kernel(const float* __restrict__ x, float* __restrict__ out) {
    int k = blockIdx.x;
    unsigned long long key = ~g_best[k * GB_STRIDE];
    unsigned idx = (unsigned)(key & 0xFFFFFFFFull);
    out[k * NFEAT + threadIdx.x] = x[(size_t)idx * NFEAT + threadIdx.x];
    __syncthreads();
    if (threadIdx.x == 0) g_best[k * GB_STRIDE] = 0ull;   // reset for next replay
}

extern "C" void kernel_launch(void* const* d_in, const int* in_sizes, int n_in,
                              void* d_out, int out_size) {
    const float* x;
    const float* cc;
    if (n_in >= 2 && in_sizes[0] == NCLUST * NFEAT) {
        cc = (const float*)d_in[0];
        x  = (const float*)d_in[1];
    } else {
        x  = (const float*)d_in[0];
        cc = (const float*)d_in[1];
    }
    float* out = (float*)d_out;

    cudaFuncSetAttribute(cluster_main,
                         cudaFuncAttributeMaxDynamicSharedMemorySize, SM_TOTAL);

    cluster_main<<<GRID_MAIN, 256, SM_TOTAL>>>(x, cc);
    gather_kernel<<<NCLUST, NFEAT>>>(x, out);
}

// round 5
// speedup vs baseline: 2.0029x; 1.1393x over previous
#include <cuda_runtime.h>
#include <cuda_fp16.h>
#include <cstdint>

#define N_TOKENS   1000000
#define NFEAT      128
#define NCLUST     64
#define TILE_TOK   128
#define NUM_TILES  ((N_TOKENS + TILE_TOK - 1) / TILE_TOK)   // 7813
#define GRID_MAIN  148
#define GB_STRIDE  16

// ---- smem layout (byte offsets) ----
#define SM_RAW   0                           // 2 x 64KB fp32 staging (swizzled 16B chunks)
#define SM_XHI   131072
#define SM_XLO   (SM_XHI + 32768)
#define SM_CHI   (SM_XLO + 32768)
#define SM_CLO   (SM_CHI + 16384)
#define SM_X2    (SM_CLO + 16384)            // 128 f32
#define SM_BEST  (SM_X2 + 512)               // 64 u64
#define SM_TOTAL (SM_BEST + 512)             // 230400 <= 232448

// zero-initialized; stores ~key so empty slot (0) == +inf; merged with atomicMax
__device__ unsigned long long g_best[NCLUST * GB_STRIDE];

__device__ __forceinline__ uint32_t smem_u32(const void* p) {
    uint32_t a;
    asm("{ .reg .u64 t; cvta.to.shared.u64 t, %1; cvt.u32.u64 %0, t; }" : "=r"(a) : "l"(p));
    return a;
}
__device__ __forceinline__ void cp_async16(uint32_t dst, const void* src) {
    asm volatile("cp.async.cg.shared.global [%0], [%1], 16;" :: "r"(dst), "l"(src));
}
#define CP_COMMIT() asm volatile("cp.async.commit_group;" ::: "memory")
#define CP_WAIT1()  asm volatile("cp.async.wait_group 1;" ::: "memory")
#define BAR_PAIR(id) asm volatile("bar.sync %0, 64;" :: "r"(id) : "memory")

__device__ __forceinline__ void ldsm4(uint32_t (&r)[4], uint32_t addr) {
    asm volatile("ldmatrix.sync.aligned.m8n8.x4.shared.b16 {%0,%1,%2,%3}, [%4];"
        : "=r"(r[0]), "=r"(r[1]), "=r"(r[2]), "=r"(r[3]) : "r"(addr));
}
__device__ __forceinline__ void mma16816(float (&d)[4], const uint32_t (&a)[4],
                                         uint32_t b0, uint32_t b1) {
    asm volatile("mma.sync.aligned.m16n8k16.row.col.f32.f16.f16.f32 "
        "{%0,%1,%2,%3}, {%4,%5,%6,%7}, {%8,%9}, {%0,%1,%2,%3};"
        : "+f"(d[0]), "+f"(d[1]), "+f"(d[2]), "+f"(d[3])
        : "r"(a[0]), "r"(a[1]), "r"(a[2]), "r"(a[3]), "r"(b0), "r"(b1));
}

__device__ __forceinline__ unsigned long long inv_key(float f, unsigned idx) {
    unsigned u = __float_as_uint(f);
    u = (u & 0x80000000u) ? ~u : (u | 0x80000000u);
    return ~(((unsigned long long)u << 32) | (unsigned long long)idx);
}
__device__ __forceinline__ uint32_t pack_h2(__half a, __half b) {
    return (uint32_t)__half_as_ushort(a) | ((uint32_t)__half_as_ushort(b) << 16);
}

__device__ __forceinline__ void cvt8(const float* e, uint4& vh, uint4& vl, float& ss) {
    __half hh[8], hl[8];
    #pragma unroll
    for (int t = 0; t < 8; ++t) {
        float x0 = e[t];
        ss = fmaf(x0, x0, ss);
        __half h = __float2half_rn(x0);
        float r = x0 - __half2float(h);
        hh[t] = h;
        hl[t] = __float2half_rn(r);
    }
    vh.x = pack_h2(hh[0], hh[1]); vh.y = pack_h2(hh[2], hh[3]);
    vh.z = pack_h2(hh[4], hh[5]); vh.w = pack_h2(hh[6], hh[7]);
    vl.x = pack_h2(hl[0], hl[1]); vl.y = pack_h2(hl[2], hl[3]);
    vl.z = pack_h2(hl[4], hl[5]); vl.w = pack_h2(hl[6], hl[7]);
}

__global__ __launch_bounds__(256, 1)
void cluster_main(const float* __restrict__ x, const float* __restrict__ cc) {
    extern __shared__ char smem[];
    const uint32_t sm = smem_u32(smem);
    const int tid  = threadIdx.x;
    const int wid  = tid >> 5;
    const int lane = tid & 31;

    const int strip = wid >> 1;            // 0..3 : 32-token strip
    const int tb    = strip * 32;          // strip token base within tile
    const int cb    = (wid & 1) * 32;      // cluster half
    const int rbase = tb + (wid & 1) * 16; // 16 rows this warp converts/loads
    const int barid = strip + 1;           // named barrier per pair

    float* x2s = (float*)(smem + SM_X2);
    unsigned long long* best_blk = (unsigned long long*)(smem + SM_BEST);
    if (tid < NCLUST) best_blk[tid] = 0ull;

    // ---- convert centers (once, block-wide) ----
    if (tid < 128) {
        int rr = tid >> 1, hh = tid & 1;
        const float* cg = cc + rr * NFEAT + hh * 64;
        float dummy = 0.f;
        #pragma unroll
        for (int c = 0; c < 8; ++c) {
            float e[8];
            #pragma unroll
            for (int t = 0; t < 8; ++t) e[t] = cg[c * 8 + t];
            uint4 vh, vl;
            cvt8(e, vh, vl, dummy);
            uint32_t phys = (uint32_t)(((hh * 8 + c) ^ (rr & 7)) * 16) + (uint32_t)rr * 256;
            *(uint4*)(smem + SM_CHI + phys) = vh;
            *(uint4*)(smem + SM_CLO + phys) = vl;
        }
    }

    // ---- ldmatrix lane addressing ----
    const int rowA  = tb + (lane & 15);
    const int khA   = lane >> 4;
    const int nrowB = cb + (lane & 7) + ((lane >> 4) & 1) * 8;
    const int khB   = (lane >> 3) & 1;

    float    bestd[8];
    unsigned besti[8];
    #pragma unroll
    for (int j = 0; j < 8; ++j) { bestd[j] = __int_as_float(0x7f800000); besti[j] = 0u; }

    const float4* xg4 = (const float4*)x;

    int ntiles = 0;
    for (int t = blockIdx.x; t < NUM_TILES; t += GRID_MAIN) ++ntiles;

    // ---- per-warp cp.async: this warp's 16 rows (8KB) of a tile ----
    auto issue_rows = [&](int tile_idx, int buf) {
        const int tokBase = tile_idx * TILE_TOK;
        const uint32_t base = sm + SM_RAW + (uint32_t)buf * 65536;
        #pragma unroll
        for (int i = 0; i < 16; ++i) {
            int f   = lane + i * 32;             // 0..511 within warp region
            int tl  = rbase + (f >> 5);          // tile row
            int dq  = f & 31;
            int gtok = tokBase + tl;
            if (gtok >= N_TOKENS) gtok = N_TOKENS - 1;
            uint32_t dst = base + (uint32_t)tl * 512
                         + (uint32_t)((dq ^ (((tl & 3) << 1) | (dq >> 4))) * 16);
            cp_async16(dst, xg4 + (size_t)gtok * 32 + dq);
        }
    };

    int tile = blockIdx.x;
    if (ntiles > 0) issue_rows(tile, 0);
    CP_COMMIT();
    __syncthreads();     // centers + best_blk ready (one-time)

    const int crow = rbase + (lane >> 1);    // row this lane converts (half-row)
    const int chal = lane & 1;

    for (int it = 0; it < ntiles; ++it, tile += GRID_MAIN) {
        const int tokBase = tile * TILE_TOK;
        const int buf = it & 1;

        if (it + 1 < ntiles) issue_rows(tile + GRID_MAIN, buf ^ 1);
        CP_COMMIT();
        CP_WAIT1();                       // own rows of tile it resident

        // ---- convert own 16 rows -> XHI/XLO; fused x^2 ----
        {
            const char* raw = smem + SM_RAW + (size_t)buf * 65536 + (size_t)crow * 512;
            const int xorv = ((crow & 3) << 1) | chal;
            float ss = 0.f;
            #pragma unroll
            for (int c = 0; c < 8; ++c) {
                int a0 = chal * 16 + 2 * c;
                float e[8];
                *(float4*)(e)     = *(const float4*)(raw + ((a0       ^ xorv) * 16));
                *(float4*)(e + 4) = *(const float4*)(raw + (((a0 + 1) ^ xorv) * 16));
                uint4 vh, vl;
                cvt8(e, vh, vl, ss);
                uint32_t phys = (uint32_t)crow * 256
                              + (uint32_t)(((chal * 8 + c) ^ (crow & 7)) * 16);
                *(uint4*)(smem + SM_XHI + phys) = vh;
                *(uint4*)(smem + SM_XLO + phys) = vl;
            }
            float tot = ss + __shfl_xor_sync(0xffffffffu, ss, 1);
            if (chal == 0) x2s[crow] = tot;
        }
        BAR_PAIR(barid);                  // pair's 32 rows converted

        // ---- MMA: 3 split terms x 8 k-steps (strip-local) ----
        float d[2][4][4];
        #pragma unroll
        for (int mt = 0; mt < 2; ++mt)
            #pragma unroll
            for (int nt = 0; nt < 4; ++nt)
                #pragma unroll
                for (int i = 0; i < 4; ++i) d[mt][nt][i] = 0.f;

        #pragma unroll
        for (int term = 0; term < 3; ++term) {
            const uint32_t abase = sm + ((term == 2) ? SM_XLO : SM_XHI);
            const uint32_t bbase = sm + ((term == 1) ? SM_CLO : SM_CHI);
            #pragma unroll
            for (int k = 0; k < 8; ++k) {
                uint32_t aF[2][4], bF[2][4];
                const int ca  = 2 * k + khA;
                const int cbk = 2 * k + khB;
                #pragma unroll
                for (int mt = 0; mt < 2; ++mt) {
                    int r = rowA + mt * 16;
                    ldsm4(aF[mt], abase + (uint32_t)(r * 256 + ((ca ^ (r & 7)) * 16)));
                }
                #pragma unroll
                for (int np = 0; np < 2; ++np) {
                    int r = nrowB + np * 16;
                    ldsm4(bF[np], bbase + (uint32_t)(r * 256 + ((cbk ^ (r & 7)) * 16)));
                }
                #pragma unroll
                for (int mt = 0; mt < 2; ++mt) {
                    mma16816(d[mt][0], aF[mt], bF[0][0], bF[0][1]);
                    mma16816(d[mt][1], aF[mt], bF[0][2], bF[0][3]);
                    mma16816(d[mt][2], aF[mt], bF[1][0], bF[1][1]);
                    mma16816(d[mt][3], aF[mt], bF[1][2], bF[1][3]);
                }
            }
        }

        // ---- epilogue: score = x^2 - 2*dot; running argmin ----
        #pragma unroll
        for (int mt = 0; mt < 2; ++mt) {
            #pragma unroll
            for (int h = 0; h < 2; ++h) {
                const int tloc = tb + mt * 16 + (lane >> 2) + h * 8;
                const int gtok = tokBase + tloc;
                if (gtok < N_TOKENS) {
                    const float xv = x2s[tloc];
                    #pragma unroll
                    for (int nt = 0; nt < 4; ++nt) {
                        #pragma unroll
                        for (int p = 0; p < 2; ++p) {
                            float s = fmaf(-2.f, d[mt][nt][h * 2 + p], xv);
                            int j = nt * 2 + p;
                            if (s < bestd[j]) { bestd[j] = s; besti[j] = (unsigned)gtok; }
                        }
                    }
                }
            }
        }
        BAR_PAIR(barid);                  // pair done reading before next convert
    }

    // ---- merge: shfl reduce then atomics ----
    #pragma unroll
    for (int j = 0; j < 8; ++j) {
        unsigned long long key = inv_key(bestd[j], besti[j]);
        #pragma unroll
        for (int off = 4; off < 32; off <<= 1) {
            unsigned long long o = __shfl_xor_sync(0xffffffffu, key, off);
            if (o > key) key = o;
        }
        if ((lane >> 2) == 0) {
            int cl = cb + (j >> 1) * 8 + 2 * (lane & 3) + (j & 1);
            atomicMax(&best_blk[cl], key);
        }
    }
    __syncthreads();
    if (tid < NCLUST)
        atomicMax(&g_best[tid * GB_STRIDE], best_blk[tid]);
}

__global__ void gather_kernel(const float* __restrict__ x, float* __restrict__ out) {
    int k = blockIdx.x;
    unsigned long long key = ~g_best[k * GB_STRIDE];
    unsigned idx = (unsigned)(key & 0xFFFFFFFFull);
    out[k * NFEAT + threadIdx.x] = x[(size_t)idx * NFEAT + threadIdx.x];
    __syncthreads();
    if (threadIdx.x == 0) g_best[k * GB_STRIDE] = 0ull;   // reset for next replay
}

extern "C" void kernel_launch(void* const* d_in, const int* in_sizes, int n_in,
                              void* d_out, int out_size) {
    const float* x;
    const float* cc;
    if (n_in >= 2 && in_sizes[0] == NCLUST * NFEAT) {
        cc = (const float*)d_in[0];
        x  = (const float*)d_in[1];
    } else {
        x  = (const float*)d_in[0];
        cc = (const float*)d_in[1];
    }
    float* out = (float*)d_out;

    cudaFuncSetAttribute(cluster_main,
                         cudaFuncAttributeMaxDynamicSharedMemorySize, SM_TOTAL);

    cluster_main<<<GRID_MAIN, 256, SM_TOTAL>>>(x, cc);
    gather_kernel<<<NCLUST, NFEAT>>>(x, out);
}

// round 6
// speedup vs baseline: 2.0068x; 1.0020x over previous
#include <cuda_runtime.h>
#include <cuda_fp16.h>
#include <cstdint>

#define N_TOKENS   1000000
#define NFEAT      128
#define NCLUST     64
#define TILE_TOK   128
#define NUM_TILES  ((N_TOKENS + TILE_TOK - 1) / TILE_TOK)   // 7813
#define GRID_MAIN  148
#define GB_STRIDE  16

// ---- smem layout (byte offsets) ----
#define SM_RAW   0                           // 2 x 64KB fp32 staging (swizzled 16B chunks)
#define SM_XHI   131072
#define SM_XLO   (SM_XHI + 32768)
#define SM_CHI   (SM_XLO + 32768)
#define SM_CLO   (SM_CHI + 16384)
#define SM_X2    (SM_CLO + 16384)            // 128 f32
#define SM_BEST  (SM_X2 + 512)               // 64 u64
#define SM_TOTAL (SM_BEST + 512)             // 230400 <= 232448

// zero-initialized; stores ~key so empty slot (0) == +inf; merged with atomicMax
__device__ unsigned long long g_best[NCLUST * GB_STRIDE];

__device__ __forceinline__ uint32_t smem_u32(const void* p) {
    uint32_t a;
    asm("{ .reg .u64 t; cvta.to.shared.u64 t, %1; cvt.u32.u64 %0, t; }" : "=r"(a) : "l"(p));
    return a;
}
__device__ __forceinline__ void cp_async16(uint32_t dst, const void* src) {
    asm volatile("cp.async.cg.shared.global [%0], [%1], 16;" :: "r"(dst), "l"(src));
}
#define CP_COMMIT() asm volatile("cp.async.commit_group;" ::: "memory")
#define CP_WAIT1()  asm volatile("cp.async.wait_group 1;" ::: "memory")
#define BAR_PAIR(id) asm volatile("bar.sync %0, 64;" :: "r"(id) : "memory")

__device__ __forceinline__ void ldsm4(uint32_t (&r)[4], uint32_t addr) {
    asm volatile("ldmatrix.sync.aligned.m8n8.x4.shared.b16 {%0,%1,%2,%3}, [%4];"
        : "=r"(r[0]), "=r"(r[1]), "=r"(r[2]), "=r"(r[3]) : "r"(addr));
}
__device__ __forceinline__ void mma16816(float (&d)[4], const uint32_t (&a)[4],
                                         uint32_t b0, uint32_t b1) {
    asm volatile("mma.sync.aligned.m16n8k16.row.col.f32.f16.f16.f32 "
        "{%0,%1,%2,%3}, {%4,%5,%6,%7}, {%8,%9}, {%0,%1,%2,%3};"
        : "+f"(d[0]), "+f"(d[1]), "+f"(d[2]), "+f"(d[3])
        : "r"(a[0]), "r"(a[1]), "r"(a[2]), "r"(a[3]), "r"(b0), "r"(b1));
}

__device__ __forceinline__ unsigned long long inv_key(float f, unsigned idx) {
    unsigned u = __float_as_uint(f);
    u = (u & 0x80000000u) ? ~u : (u | 0x80000000u);
    return ~(((unsigned long long)u << 32) | (unsigned long long)idx);
}
__device__ __forceinline__ uint32_t pack_h2(__half a, __half b) {
    return (uint32_t)__half_as_ushort(a) | ((uint32_t)__half_as_ushort(b) << 16);
}

__device__ __forceinline__ void cvt8(const float* e, uint4& vh, uint4& vl, float& ss) {
    __half hh[8], hl[8];
    #pragma unroll
    for (int t = 0; t < 8; ++t) {
        float x0 = e[t];
        ss = fmaf(x0, x0, ss);
        __half h = __float2half_rn(x0);
        float r = x0 - __half2float(h);
        hh[t] = h;
        hl[t] = __float2half_rn(r);
    }
    vh.x = pack_h2(hh[0], hh[1]); vh.y = pack_h2(hh[2], hh[3]);
    vh.z = pack_h2(hh[4], hh[5]); vh.w = pack_h2(hh[6], hh[7]);
    vl.x = pack_h2(hl[0], hl[1]); vl.y = pack_h2(hl[2], hl[3]);
    vl.z = pack_h2(hl[4], hl[5]); vl.w = pack_h2(hl[6], hl[7]);
}

__global__ __launch_bounds__(256, 1)
void cluster_main(const float* __restrict__ x, const float* __restrict__ cc) {
    extern __shared__ char smem[];
    const uint32_t sm = smem_u32(smem);
    const int tid  = threadIdx.x;
    const int wid  = tid >> 5;
    const int lane = tid & 31;

    const int strip = wid >> 1;            // 0..3 : 32-token strip
    const int tb    = strip * 32;          // strip token base within tile
    const int cb    = (wid & 1) * 32;      // cluster half
    const int rbase = tb + (wid & 1) * 16; // 16 rows this warp converts/loads
    const int barid = strip + 1;           // named barrier per pair

    float* x2s = (float*)(smem + SM_X2);
    unsigned long long* best_blk = (unsigned long long*)(smem + SM_BEST);
    if (tid < NCLUST) best_blk[tid] = 0ull;

    // ---- convert centers (once, block-wide) ----
    if (tid < 128) {
        int rr = tid >> 1, hh = tid & 1;
        const float* cg = cc + rr * NFEAT + hh * 64;
        float dummy = 0.f;
        #pragma unroll
        for (int c = 0; c < 8; ++c) {
            float e[8];
            #pragma unroll
            for (int t = 0; t < 8; ++t) e[t] = cg[c * 8 + t];
            uint4 vh, vl;
            cvt8(e, vh, vl, dummy);
            uint32_t phys = (uint32_t)(((hh * 8 + c) ^ (rr & 7)) * 16) + (uint32_t)rr * 256;
            *(uint4*)(smem + SM_CHI + phys) = vh;
            *(uint4*)(smem + SM_CLO + phys) = vl;
        }
    }

    // ---- ldmatrix lane addressing ----
    const int rowA  = tb + (lane & 15);
    const int khA   = lane >> 4;
    const int nrowB = cb + (lane & 7) + ((lane >> 4) & 1) * 8;
    const int khB   = (lane >> 3) & 1;

    float    bestd[8];
    unsigned besti[8];
    #pragma unroll
    for (int j = 0; j < 8; ++j) { bestd[j] = __int_as_float(0x7f800000); besti[j] = 0u; }

    const float4* xg4 = (const float4*)x;

    int ntiles = 0;
    for (int t = blockIdx.x; t < NUM_TILES; t += GRID_MAIN) ++ntiles;

    // ---- per-warp cp.async: this warp's 16 rows (8KB) of a tile ----
    auto issue_rows = [&](int tile_idx, int buf) {
        const int tokBase = tile_idx * TILE_TOK;
        const uint32_t base = sm + SM_RAW + (uint32_t)buf * 65536;
        #pragma unroll
        for (int i = 0; i < 16; ++i) {
            int f   = lane + i * 32;             // 0..511 within warp region
            int tl  = rbase + (f >> 5);          // tile row
            int dq  = f & 31;
            int gtok = tokBase + tl;
            if (gtok >= N_TOKENS) gtok = N_TOKENS - 1;
            uint32_t dst = base + (uint32_t)tl * 512
                         + (uint32_t)((dq ^ (((tl & 3) << 1) | (dq >> 4))) * 16);
            cp_async16(dst, xg4 + (size_t)gtok * 32 + dq);
        }
    };

    int tile = blockIdx.x;
    if (ntiles > 0) issue_rows(tile, 0);
    CP_COMMIT();
    __syncthreads();     // centers + best_blk ready (one-time)

    const int crow = rbase + (lane >> 1);    // row this lane converts (half-row)
    const int chal = lane & 1;

    for (int it = 0; it < ntiles; ++it, tile += GRID_MAIN) {
        const int tokBase = tile * TILE_TOK;
        const int buf = it & 1;

        if (it + 1 < ntiles) issue_rows(tile + GRID_MAIN, buf ^ 1);
        CP_COMMIT();
        CP_WAIT1();                       // own rows of tile it resident

        // ---- convert own 16 rows -> XHI/XLO; fused x^2 ----
        {
            const char* raw = smem + SM_RAW + (size_t)buf * 65536 + (size_t)crow * 512;
            const int xorv = ((crow & 3) << 1) | chal;
            float ss = 0.f;
            #pragma unroll
            for (int c = 0; c < 8; ++c) {
                int a0 = chal * 16 + 2 * c;
                float e[8];
                *(float4*)(e)     = *(const float4*)(raw + ((a0       ^ xorv) * 16));
                *(float4*)(e + 4) = *(const float4*)(raw + (((a0 + 1) ^ xorv) * 16));
                uint4 vh, vl;
                cvt8(e, vh, vl, ss);
                uint32_t phys = (uint32_t)crow * 256
                              + (uint32_t)(((chal * 8 + c) ^ (crow & 7)) * 16);
                *(uint4*)(smem + SM_XHI + phys) = vh;
                *(uint4*)(smem + SM_XLO + phys) = vl;
            }
            float tot = ss + __shfl_xor_sync(0xffffffffu, ss, 1);
            if (chal == 0) x2s[crow] = tot;
        }
        BAR_PAIR(barid);                  // pair's 32 rows converted

        // ---- MMA: 3 split terms x 8 k-steps (strip-local) ----
        float d[2][4][4];
        #pragma unroll
        for (int mt = 0; mt < 2; ++mt)
            #pragma unroll
            for (int nt = 0; nt < 4; ++nt)
                #pragma unroll
                for (int i = 0; i < 4; ++i) d[mt][nt][i] = 0.f;

        #pragma unroll
        for (int term = 0; term < 3; ++term) {
            const uint32_t abase = sm + ((term == 2) ? SM_XLO : SM_XHI);
            const uint32_t bbase = sm + ((term == 1) ? SM_CLO : SM_CHI);
            #pragma unroll
            for (int k = 0; k < 8; ++k) {
                uint32_t aF[2][4], bF[2][4];
                const int ca  = 2 * k + khA;
                const int cbk = 2 * k + khB;
                #pragma unroll
                for (int mt = 0; mt < 2; ++mt) {
                    int r = rowA + mt * 16;
                    ldsm4(aF[mt], abase + (uint32_t)(r * 256 + ((ca ^ (r & 7)) * 16)));
                }
                #pragma unroll
                for (int np = 0; np < 2; ++np) {
                    int r = nrowB + np * 16;
                    ldsm4(bF[np], bbase + (uint32_t)(r * 256 + ((cbk ^ (r & 7)) * 16)));
                }
                #pragma unroll
                for (int mt = 0; mt < 2; ++mt) {
                    mma16816(d[mt][0], aF[mt], bF[0][0], bF[0][1]);
                    mma16816(d[mt][1], aF[mt], bF[0][2], bF[0][3]);
                    mma16816(d[mt][2], aF[mt], bF[1][0], bF[1][1]);
                    mma16816(d[mt][3], aF[mt], bF[1][2], bF[1][3]);
                }
            }
        }

        // ---- epilogue: score = x^2 - 2*dot; running argmin ----
        #pragma unroll
        for (int mt = 0; mt < 2; ++mt) {
            #pragma unroll
            for (int h = 0; h < 2; ++h) {
                const int tloc = tb + mt * 16 + (lane >> 2) + h * 8;
                const int gtok = tokBase + tloc;
                if (gtok < N_TOKENS) {
                    const float xv = x2s[tloc];
                    #pragma unroll
                    for (int nt = 0; nt < 4; ++nt) {
                        #pragma unroll
                        for (int p = 0; p < 2; ++p) {
                            float s = fmaf(-2.f, d[mt][nt][h * 2 + p], xv);
                            int j = nt * 2 + p;
                            if (s < bestd[j]) { bestd[j] = s; besti[j] = (unsigned)gtok; }
                        }
                    }
                }
            }
        }
        BAR_PAIR(barid);                  // pair done reading before next convert
    }

    // ---- merge: shfl reduce then atomics ----
    #pragma unroll
    for (int j = 0; j < 8; ++j) {
        unsigned long long key = inv_key(bestd[j], besti[j]);
        #pragma unroll
        for (int off = 4; off < 32; off <<= 1) {
            unsigned long long o = __shfl_xor_sync(0xffffffffu, key, off);
            if (o > key) key = o;
        }
        if ((lane >> 2) == 0) {
            int cl = cb + (j >> 1) * 8 + 2 * (lane & 3) + (j & 1);
            atomicMax(&best_blk[cl], key);
        }
    }
    __syncthreads();
    if (tid < NCLUST)
        atomicMax(&g_best[tid * GB_STRIDE], best_blk[tid]);
}

__global__ void gather_kernel(const float* __restrict__ x, float* __restrict__ out) {
    int k = blockIdx.x;
    unsigned long long key = ~g_best[k * GB_STRIDE];
    unsigned idx = (unsigned)(key & 0xFFFFFFFFull);
    out[k * NFEAT + threadIdx.x] = x[(size_t)idx * NFEAT + threadIdx.x];
    __syncthreads();
    if (threadIdx.x == 0) g_best[k * GB_STRIDE] = 0ull;   // reset for next replay
}

extern "C" void kernel_launch(void* const* d_in, const int* in_sizes, int n_in,
                              void* d_out, int out_size) {
    const float* x;
    const float* cc;
    if (n_in >= 2 && in_sizes[0] == NCLUST * NFEAT) {
        cc = (const float*)d_in[0];
        x  = (const float*)d_in[1];
    } else {
        x  = (const float*)d_in[0];
        cc = (const float*)d_in[1];
    }
    float* out = (float*)d_out;

    cudaFuncSetAttribute(cluster_main,
                         cudaFuncAttributeMaxDynamicSharedMemorySize, SM_TOTAL);

    cluster_main<<<GRID_MAIN, 256, SM_TOTAL>>>(x, cc);
    gather_kernel<<<NCLUST, NFEAT>>>(x, out);
}